// round 9
// baseline (speedup 1.0000x reference)
#include <cuda_runtime.h>

#define NN 100000
#define EE 1200000
#define NB 98            // ceil(NN / 1024)

// ---------------- scratch (device globals; no allocation allowed) ------------
__device__ __align__(16) int   g_degi[NN];
__device__ __align__(16) int   g_cnt [NN];
__device__ __align__(16) int   g_ptr [NN];        // CSR row start (exclusive scan)
__device__ __align__(16) int   g_bsum[NB];
__device__ __align__(16) float g_dis [NN];
__device__ __align__(16) int2  g_csr_cw[EE];      // packed {col, w-as-bits}
__device__ __align__(16) float g_H  [(size_t)NN * 64];  // layer1: C0 (+b1), then += P(B)
__device__ __align__(16) float g_B  [(size_t)NN * 64];  // layer1: C1, then += 2P(C2)
__device__ __align__(16) float g_C2 [(size_t)NN * 64];  // layer1: x@W1[2]
__device__ __align__(16) float g_B2 [(size_t)NN * 32];  // layer2: C1', then += 2P(C2')
__device__ __align__(16) float g_C22[(size_t)NN * 32];  // layer2: relu(H)@W2[2]

// ---------------- f32x2 packed helpers ---------------------------------------
__device__ __forceinline__ unsigned long long pk2(float lo, float hi) {
    unsigned long long r;
    asm("mov.b64 %0, {%1, %2};" : "=l"(r) : "f"(lo), "f"(hi));
    return r;
}
__device__ __forceinline__ unsigned long long ffma2(unsigned long long a,
                                                    unsigned long long b,
                                                    unsigned long long c) {
    unsigned long long d;
    asm("fma.rn.f32x2 %0, %1, %2, %3;" : "=l"(d) : "l"(a), "l"(b), "l"(c));
    return d;
}
__device__ __forceinline__ void upk2(unsigned long long v, float& lo, float& hi) {
    asm("mov.b64 {%0, %1}, %2;" : "=f"(lo), "=f"(hi) : "l"(v));
}

// ---------------- degree / CSR build -----------------------------------------
__global__ void k_init() {
    int i = blockIdx.x * blockDim.x + threadIdx.x;
    if (i < NN) { g_degi[i] = 0; g_cnt[i] = 0; }
}

__global__ void k_deg(const int* __restrict__ row) {
    int e = blockIdx.x * blockDim.x + threadIdx.x;
    if (e < EE) {
        int r = row[e];
        if (r >= 0 && r < NN) atomicAdd(&g_degi[r], 1);
    }
}

__global__ __launch_bounds__(1024) void k_scan1() {
    __shared__ int s[1024];
    int i = blockIdx.x * 1024 + threadIdx.x;
    int v = (i < NN) ? g_degi[i] : 0;
    s[threadIdx.x] = v;
    __syncthreads();
    for (int off = 1; off < 1024; off <<= 1) {
        int a = (threadIdx.x >= off) ? s[threadIdx.x - off] : 0;
        __syncthreads();
        s[threadIdx.x] += a;
        __syncthreads();
    }
    if (i < NN) g_ptr[i] = s[threadIdx.x] - v;      // exclusive scan within block
    if (threadIdx.x == 1023) g_bsum[blockIdx.x] = s[1023];
}

// fixup: add prefix of block sums (per-block shared reduction) + deg^{-1/2}
__global__ __launch_bounds__(1024) void k_scan3() {
    __shared__ int s[128];
    const int b = blockIdx.x;
    const int t = threadIdx.x;
    if (t < 128) s[t] = (t < b) ? g_bsum[t] : 0;    // b <= NB-1 < 128
    __syncthreads();
    for (int o = 64; o > 0; o >>= 1) {
        if (t < o) s[t] += s[t + o];
        __syncthreads();
    }
    const int off = s[0];
    int i = b * 1024 + t;
    if (i < NN) {
        g_ptr[i] += off;
        int d = g_degi[i];
        g_dis[i] = (d > 0) ? rsqrtf((float)d) : 0.f;
    }
}

__global__ void k_fill(const int* __restrict__ row, const int* __restrict__ col) {
    int e = blockIdx.x * blockDim.x + threadIdx.x;
    if (e < EE) {
        int r = row[e];
        int c = col[e];
        if (r < 0 || r >= NN || c < 0 || c >= NN) return;
        int slot = g_ptr[r] + atomicAdd(&g_cnt[r], 1);
        float w = g_dis[r] * g_dis[c];
        g_csr_cw[slot] = make_int2(c, __float_as_int(w));
    }
}

// ---------------- fused GEMM, layer 1: x[N,64] -> {H, B, C2} in one kernel ---
__global__ __launch_bounds__(128) void k_gemm1(const float* __restrict__ x,
                                               const float* __restrict__ W1,
                                               const float* __restrict__ b1) {
    __shared__ float sX[64][68];   // [channel][node]
    __shared__ float sW[64][64];   // [channel][outcol]
    const int n0  = blockIdx.x * 64;
    const int tid = threadIdx.x;

    for (int i = tid; i < 1024; i += 128) {
        int n = i >> 4, c4 = i & 15;
        float4 v = make_float4(0.f, 0.f, 0.f, 0.f);
        if (n0 + n < NN)
            v = reinterpret_cast<const float4*>(x)[(size_t)(n0 + n) * 16 + c4];
        sX[c4 * 4 + 0][n] = v.x; sX[c4 * 4 + 1][n] = v.y;
        sX[c4 * 4 + 2][n] = v.z; sX[c4 * 4 + 3][n] = v.w;
    }

    const int tx = tid & 15;   // 16 col groups x4 = 64 cols
    const int ty = tid >> 4;   // 8 row groups  x8 = 64 nodes

    for (int which = 0; which < 3; ++which) {
        __syncthreads();
        for (int i = tid; i < 1024; i += 128) {
            int c = i >> 4, o4 = i & 15;
            float4 w = reinterpret_cast<const float4*>(W1 + which * 4096)[c * 16 + o4];
            if (which == 0) {
                float4 w2 = reinterpret_cast<const float4*>(W1 + 2 * 4096)[c * 16 + o4];
                w.x -= w2.x; w.y -= w2.y; w.z -= w2.z; w.w -= w2.w;
            }
            reinterpret_cast<float4*>(&sW[c][0])[o4] = w;
        }
        __syncthreads();

        unsigned long long acc2[4][4];
#pragma unroll
        for (int p = 0; p < 4; p++)
#pragma unroll
            for (int j = 0; j < 4; j++) acc2[p][j] = 0ull;

#pragma unroll 8
        for (int k = 0; k < 64; ++k) {
            const unsigned long long* ap =
                reinterpret_cast<const unsigned long long*>(&sX[k][ty * 8]);
            float4 w = *reinterpret_cast<const float4*>(&sW[k][tx * 4]);
            unsigned long long w2[4] = {pk2(w.x, w.x), pk2(w.y, w.y),
                                        pk2(w.z, w.z), pk2(w.w, w.w)};
#pragma unroll
            for (int p = 0; p < 4; p++) {
                unsigned long long a = ap[p];
#pragma unroll
                for (int j = 0; j < 4; j++) acc2[p][j] = ffma2(a, w2[j], acc2[p][j]);
            }
        }

        float4 bv = make_float4(0.f, 0.f, 0.f, 0.f);
        if (which == 0) bv = reinterpret_cast<const float4*>(b1)[tx];
        float* dst = (which == 0) ? g_H : (which == 1) ? g_B : g_C2;
#pragma unroll
        for (int p = 0; p < 4; p++) {
            float lo[4], hi[4];
#pragma unroll
            for (int j = 0; j < 4; j++) upk2(acc2[p][j], lo[j], hi[j]);
            int n = n0 + ty * 8 + p * 2;
            if (n < NN)
                reinterpret_cast<float4*>(dst)[(size_t)n * 16 + tx] =
                    make_float4(lo[0] + bv.x, lo[1] + bv.y, lo[2] + bv.z, lo[3] + bv.w);
            if (n + 1 < NN)
                reinterpret_cast<float4*>(dst)[(size_t)(n + 1) * 16 + tx] =
                    make_float4(hi[0] + bv.x, hi[1] + bv.y, hi[2] + bv.z, hi[3] + bv.w);
        }
    }
}

// ---------------- fused GEMM, layer 2: relu(H)[N,64] -> {out, B2, C22} -------
__global__ __launch_bounds__(128) void k_gemm2(float* __restrict__ out,
                                               const float* __restrict__ W2,
                                               const float* __restrict__ b2) {
    __shared__ float sX[64][132];
    __shared__ float sW[64][32];
    const int n0  = blockIdx.x * 128;
    const int tid = threadIdx.x;

    for (int i = tid; i < 2048; i += 128) {
        int n = i >> 4, c4 = i & 15;
        float4 v = make_float4(0.f, 0.f, 0.f, 0.f);
        if (n0 + n < NN) {
            v = reinterpret_cast<const float4*>(g_H)[(size_t)(n0 + n) * 16 + c4];
            v.x = fmaxf(v.x, 0.f); v.y = fmaxf(v.y, 0.f);
            v.z = fmaxf(v.z, 0.f); v.w = fmaxf(v.w, 0.f);
        }
        sX[c4 * 4 + 0][n] = v.x; sX[c4 * 4 + 1][n] = v.y;
        sX[c4 * 4 + 2][n] = v.z; sX[c4 * 4 + 3][n] = v.w;
    }

    const int tx = tid & 7;    // 8 col groups x4 = 32 cols
    const int ty = tid >> 3;   // 16 row groups x8 = 128 nodes

    for (int which = 0; which < 3; ++which) {
        __syncthreads();
        for (int i = tid; i < 512; i += 128) {
            int c = i >> 3, o4 = i & 7;
            float4 w = reinterpret_cast<const float4*>(W2 + which * 2048)[c * 8 + o4];
            if (which == 0) {
                float4 w2 = reinterpret_cast<const float4*>(W2 + 2 * 2048)[c * 8 + o4];
                w.x -= w2.x; w.y -= w2.y; w.z -= w2.z; w.w -= w2.w;
            }
            reinterpret_cast<float4*>(&sW[c][0])[o4] = w;
        }
        __syncthreads();

        unsigned long long acc2[4][4];
#pragma unroll
        for (int p = 0; p < 4; p++)
#pragma unroll
            for (int j = 0; j < 4; j++) acc2[p][j] = 0ull;

#pragma unroll 8
        for (int k = 0; k < 64; ++k) {
            const unsigned long long* ap =
                reinterpret_cast<const unsigned long long*>(&sX[k][ty * 8]);
            float4 w = *reinterpret_cast<const float4*>(&sW[k][tx * 4]);
            unsigned long long w2[4] = {pk2(w.x, w.x), pk2(w.y, w.y),
                                        pk2(w.z, w.z), pk2(w.w, w.w)};
#pragma unroll
            for (int p = 0; p < 4; p++) {
                unsigned long long a = ap[p];
#pragma unroll
                for (int j = 0; j < 4; j++) acc2[p][j] = ffma2(a, w2[j], acc2[p][j]);
            }
        }

        float4 bv = make_float4(0.f, 0.f, 0.f, 0.f);
        if (which == 0) bv = reinterpret_cast<const float4*>(b2)[tx];
        float* dst = (which == 0) ? out : (which == 1) ? g_B2 : g_C22;
#pragma unroll
        for (int p = 0; p < 4; p++) {
            float lo[4], hi[4];
#pragma unroll
            for (int j = 0; j < 4; j++) upk2(acc2[p][j], lo[j], hi[j]);
            int n = n0 + ty * 8 + p * 2;
            if (n < NN)
                reinterpret_cast<float4*>(dst)[(size_t)n * 8 + tx] =
                    make_float4(lo[0] + bv.x, lo[1] + bv.y, lo[2] + bv.z, lo[3] + bv.w);
            if (n + 1 < NN)
                reinterpret_cast<float4*>(dst)[(size_t)(n + 1) * 8 + tx] =
                    make_float4(hi[0] + bv.x, hi[1] + bv.y, hi[2] + bv.z, hi[3] + bv.w);
        }
    }
}

// ---------------- pull-style propagation: dst[r] += scale * sum_e w*src[col] -
template <int G, int MODE>
__global__ __launch_bounds__(256) void k_prop(float* __restrict__ dout, float scale) {
    unsigned t = blockIdx.x * 256u + threadIdx.x;
    unsigned r = t / G;
    unsigned g = t & (G - 1);
    if (r >= NN) return;

    const float* src;
    float* dst;
    if (MODE == 0)      { src = g_C2;  dst = g_B;  }
    else if (MODE == 1) { src = g_B;   dst = g_H;  }
    else if (MODE == 2) { src = g_C22; dst = g_B2; }
    else                { src = g_B2;  dst = dout; }

    int e  = g_ptr[r];
    int e1 = (r == NN - 1) ? EE : g_ptr[r + 1];

    float4 a0 = make_float4(0.f, 0.f, 0.f, 0.f);
    float4 a1 = make_float4(0.f, 0.f, 0.f, 0.f);
    for (; e + 1 < e1; e += 2) {
        int2 cw0 = __ldg(&g_csr_cw[e]);
        int2 cw1 = __ldg(&g_csr_cw[e + 1]);
        float w0 = __int_as_float(cw0.y);
        float w1 = __int_as_float(cw1.y);
        float4 v0 = reinterpret_cast<const float4*>(src)[(size_t)cw0.x * G + g];
        float4 v1 = reinterpret_cast<const float4*>(src)[(size_t)cw1.x * G + g];
        a0.x += w0 * v0.x; a0.y += w0 * v0.y; a0.z += w0 * v0.z; a0.w += w0 * v0.w;
        a1.x += w1 * v1.x; a1.y += w1 * v1.y; a1.z += w1 * v1.z; a1.w += w1 * v1.w;
    }
    if (e < e1) {
        int2 cw0 = __ldg(&g_csr_cw[e]);
        float w0 = __int_as_float(cw0.y);
        float4 v0 = reinterpret_cast<const float4*>(src)[(size_t)cw0.x * G + g];
        a0.x += w0 * v0.x; a0.y += w0 * v0.y; a0.z += w0 * v0.z; a0.w += w0 * v0.w;
    }
    a0.x += a1.x; a0.y += a1.y; a0.z += a1.z; a0.w += a1.w;

    float4 d = reinterpret_cast<float4*>(dst)[(size_t)r * G + g];
    d.x += scale * a0.x; d.y += scale * a0.y;
    d.z += scale * a0.z; d.w += scale * a0.w;
    reinterpret_cast<float4*>(dst)[(size_t)r * G + g] = d;
}

// ---------------- launch ------------------------------------------------------
// Fork-join: CSR build runs on a side stream concurrently with k_gemm1 (no data
// dependency). Stream/event created once on the first (non-captured) call; the
// captured work sequence is identical on every call.
extern "C" void kernel_launch(void* const* d_in, const int* in_sizes, int n_in,
                              void* d_out, int out_size) {
    const float* x   = (const float*)d_in[0];
    const int*   ei  = (const int*)d_in[1];     // int32 (JAX x64 disabled)
    const float* W1  = (const float*)d_in[2];
    const float* b1  = (const float*)d_in[3];
    const float* W2  = (const float*)d_in[4];
    const float* b2  = (const float*)d_in[5];
    float*       out = (float*)d_out;

    const int* row = ei;
    const int* col = ei + EE;

    static cudaStream_t s2 = []() {
        cudaStream_t s;
        cudaStreamCreateWithFlags(&s, cudaStreamNonBlocking);
        return s;
    }();
    static cudaEvent_t evFork = []() {
        cudaEvent_t e;
        cudaEventCreateWithFlags(&e, cudaEventDisableTiming);
        return e;
    }();
    static cudaEvent_t evJoin = []() {
        cudaEvent_t e;
        cudaEventCreateWithFlags(&e, cudaEventDisableTiming);
        return e;
    }();

    const int TB = 256;

    // fork: CSR build on s2
    cudaEventRecord(evFork, 0);
    cudaStreamWaitEvent(s2, evFork, 0);
    k_init <<<(NN + TB - 1) / TB, TB, 0, s2>>>();
    k_deg  <<<(EE + TB - 1) / TB, TB, 0, s2>>>(row);
    k_scan1<<<NB, 1024, 0, s2>>>();
    k_scan3<<<NB, 1024, 0, s2>>>();
    k_fill <<<(EE + TB - 1) / TB, TB, 0, s2>>>(row, col);
    cudaEventRecord(evJoin, s2);

    // concurrent on default stream: Layer-1 fused GEMM (only needs x, W1, b1)
    k_gemm1<<<(NN + 63) / 64, 128>>>(x, W1, b1);

    // join: props need both CSR and GEMM outputs
    cudaStreamWaitEvent(0, evJoin, 0);

    // B += 2*P(C2)   (P = -A_norm -> scale = -2)
    k_prop<16, 0><<<((unsigned)NN * 16 + TB - 1) / TB, TB>>>(out, -2.0f);
    // H += P(B)
    k_prop<16, 1><<<((unsigned)NN * 16 + TB - 1) / TB, TB>>>(out, -1.0f);

    // Layer 2 (relu on load): out = relu(H)@(W0'-W2')+b2, B2, C22
    k_gemm2<<<(NN + 127) / 128, 128>>>(out, W2, b2);
    // B2 += 2*P(C22)
    k_prop<8, 2><<<((unsigned)NN * 8 + TB - 1) / TB, TB>>>(out, -2.0f);
    // out += P(B2)
    k_prop<8, 3><<<((unsigned)NN * 8 + TB - 1) / TB, TB>>>(out, -1.0f);
}

// round 10
// speedup vs baseline: 1.1182x; 1.1182x over previous
#include <cuda_runtime.h>
#include <cuda_fp16.h>

#define NN 100000
#define EE 1200000
#define NB 98            // ceil(NN / 1024)

// ---------------- scratch (device globals; no allocation allowed) ------------
__device__ __align__(16) int    g_degi[NN];
__device__ __align__(16) int    g_cnt [NN];
__device__ __align__(16) int    g_ptr [NN];       // CSR row start (exclusive scan)
__device__ __align__(16) int    g_bsum[NB];
__device__ __align__(16) float  g_dis [NN];
__device__ __align__(16) int2   g_csr_cw[EE];     // packed {col, w-as-bits}
// fp16 intermediates (halved gather traffic; fp32 accumulation everywhere)
__device__ __align__(16) __half g_H16  [(size_t)NN * 64]; // layer1 C0+b1, then += P(B)
__device__ __align__(16) __half g_B16  [(size_t)NN * 64]; // layer1 C1, then += 2P(C2)
__device__ __align__(16) __half g_C216 [(size_t)NN * 64]; // layer1 x@W1[2]
__device__ __align__(16) __half g_B216 [(size_t)NN * 32]; // layer2 C1', then += 2P(C2')
__device__ __align__(16) __half g_C2216[(size_t)NN * 32]; // layer2 relu(H)@W2[2]

// ---------------- packed helpers ---------------------------------------------
__device__ __forceinline__ unsigned long long pk2(float lo, float hi) {
    unsigned long long r;
    asm("mov.b64 %0, {%1, %2};" : "=l"(r) : "f"(lo), "f"(hi));
    return r;
}
__device__ __forceinline__ unsigned long long ffma2(unsigned long long a,
                                                    unsigned long long b,
                                                    unsigned long long c) {
    unsigned long long d;
    asm("fma.rn.f32x2 %0, %1, %2, %3;" : "=l"(d) : "l"(a), "l"(b), "l"(c));
    return d;
}
__device__ __forceinline__ void upk2(unsigned long long v, float& lo, float& hi) {
    asm("mov.b64 {%0, %1}, %2;" : "=f"(lo), "=f"(hi) : "l"(v));
}
__device__ __forceinline__ float2 h2f(unsigned u) {
    __half2 h = *reinterpret_cast<__half2*>(&u);
    return __half22float2(h);
}
__device__ __forceinline__ unsigned f2h(float a, float b) {
    __half2 h = __floats2half2_rn(a, b);
    return *reinterpret_cast<unsigned*>(&h);
}

// ---------------- degree / CSR build -----------------------------------------
__global__ void k_init() {
    int i = blockIdx.x * blockDim.x + threadIdx.x;
    if (i < NN) { g_degi[i] = 0; g_cnt[i] = 0; }
}

__global__ void k_deg(const int* __restrict__ row) {
    int e = blockIdx.x * blockDim.x + threadIdx.x;
    if (e < EE) {
        int r = row[e];
        if (r >= 0 && r < NN) atomicAdd(&g_degi[r], 1);
    }
}

__global__ __launch_bounds__(1024) void k_scan1() {
    __shared__ int s[1024];
    int i = blockIdx.x * 1024 + threadIdx.x;
    int v = (i < NN) ? g_degi[i] : 0;
    s[threadIdx.x] = v;
    __syncthreads();
    for (int off = 1; off < 1024; off <<= 1) {
        int a = (threadIdx.x >= off) ? s[threadIdx.x - off] : 0;
        __syncthreads();
        s[threadIdx.x] += a;
        __syncthreads();
    }
    if (i < NN) g_ptr[i] = s[threadIdx.x] - v;
    if (threadIdx.x == 1023) g_bsum[blockIdx.x] = s[1023];
}

__global__ __launch_bounds__(1024) void k_scan3() {
    __shared__ int s[128];
    const int b = blockIdx.x;
    const int t = threadIdx.x;
    if (t < 128) s[t] = (t < b) ? g_bsum[t] : 0;    // b <= NB-1 < 128
    __syncthreads();
    for (int o = 64; o > 0; o >>= 1) {
        if (t < o) s[t] += s[t + o];
        __syncthreads();
    }
    const int off = s[0];
    int i = b * 1024 + t;
    if (i < NN) {
        g_ptr[i] += off;
        int d = g_degi[i];
        g_dis[i] = (d > 0) ? rsqrtf((float)d) : 0.f;
    }
}

__global__ void k_fill(const int* __restrict__ row, const int* __restrict__ col) {
    int e = blockIdx.x * blockDim.x + threadIdx.x;
    if (e < EE) {
        int r = row[e];
        int c = col[e];
        if (r < 0 || r >= NN || c < 0 || c >= NN) return;
        int slot = g_ptr[r] + atomicAdd(&g_cnt[r], 1);
        float w = g_dis[r] * g_dis[c];
        g_csr_cw[slot] = make_int2(c, __float_as_int(w));
    }
}

// ---------------- fused GEMM, layer 1: x[N,64] -> {H16, B16, C216} -----------
__global__ __launch_bounds__(128) void k_gemm1(const float* __restrict__ x,
                                               const float* __restrict__ W1,
                                               const float* __restrict__ b1) {
    __shared__ float sX[64][68];   // [channel][node]
    __shared__ float sW[64][64];   // [channel][outcol]
    const int n0  = blockIdx.x * 64;
    const int tid = threadIdx.x;

    for (int i = tid; i < 1024; i += 128) {
        int n = i >> 4, c4 = i & 15;
        float4 v = make_float4(0.f, 0.f, 0.f, 0.f);
        if (n0 + n < NN)
            v = reinterpret_cast<const float4*>(x)[(size_t)(n0 + n) * 16 + c4];
        sX[c4 * 4 + 0][n] = v.x; sX[c4 * 4 + 1][n] = v.y;
        sX[c4 * 4 + 2][n] = v.z; sX[c4 * 4 + 3][n] = v.w;
    }

    const int tx = tid & 15;   // 16 col groups x4 = 64 cols
    const int ty = tid >> 4;   // 8 row groups  x8 = 64 nodes

    for (int which = 0; which < 3; ++which) {
        __syncthreads();
        for (int i = tid; i < 1024; i += 128) {
            int c = i >> 4, o4 = i & 15;
            float4 w = reinterpret_cast<const float4*>(W1 + which * 4096)[c * 16 + o4];
            if (which == 0) {
                float4 w2 = reinterpret_cast<const float4*>(W1 + 2 * 4096)[c * 16 + o4];
                w.x -= w2.x; w.y -= w2.y; w.z -= w2.z; w.w -= w2.w;
            }
            reinterpret_cast<float4*>(&sW[c][0])[o4] = w;
        }
        __syncthreads();

        unsigned long long acc2[4][4];
#pragma unroll
        for (int p = 0; p < 4; p++)
#pragma unroll
            for (int j = 0; j < 4; j++) acc2[p][j] = 0ull;

#pragma unroll 8
        for (int k = 0; k < 64; ++k) {
            const unsigned long long* ap =
                reinterpret_cast<const unsigned long long*>(&sX[k][ty * 8]);
            float4 w = *reinterpret_cast<const float4*>(&sW[k][tx * 4]);
            unsigned long long w2[4] = {pk2(w.x, w.x), pk2(w.y, w.y),
                                        pk2(w.z, w.z), pk2(w.w, w.w)};
#pragma unroll
            for (int p = 0; p < 4; p++) {
                unsigned long long a = ap[p];
#pragma unroll
                for (int j = 0; j < 4; j++) acc2[p][j] = ffma2(a, w2[j], acc2[p][j]);
            }
        }

        float4 bv = make_float4(0.f, 0.f, 0.f, 0.f);
        if (which == 0) bv = reinterpret_cast<const float4*>(b1)[tx];
        __half* dst = (which == 0) ? g_H16 : (which == 1) ? g_B16 : g_C216;
#pragma unroll
        for (int p = 0; p < 4; p++) {
            float lo[4], hi[4];
#pragma unroll
            for (int j = 0; j < 4; j++) upk2(acc2[p][j], lo[j], hi[j]);
            int n = n0 + ty * 8 + p * 2;
            if (n < NN)
                *reinterpret_cast<uint2*>(dst + (size_t)n * 64 + tx * 4) =
                    make_uint2(f2h(lo[0] + bv.x, lo[1] + bv.y),
                               f2h(lo[2] + bv.z, lo[3] + bv.w));
            if (n + 1 < NN)
                *reinterpret_cast<uint2*>(dst + (size_t)(n + 1) * 64 + tx * 4) =
                    make_uint2(f2h(hi[0] + bv.x, hi[1] + bv.y),
                               f2h(hi[2] + bv.z, hi[3] + bv.w));
        }
    }
}

// ---------------- fused GEMM, layer 2: relu(H16)[N,64] -> {out, B216, C2216} -
__global__ __launch_bounds__(128) void k_gemm2(float* __restrict__ out,
                                               const float* __restrict__ W2,
                                               const float* __restrict__ b2) {
    __shared__ float sX[64][132];
    __shared__ float sW[64][32];
    const int n0  = blockIdx.x * 128;
    const int tid = threadIdx.x;

    for (int i = tid; i < 1024; i += 128) {
        int n = i >> 3, c8 = i & 7;     // 128 nodes x 8 channel-groups
        uint4 v = make_uint4(0u, 0u, 0u, 0u);
        if (n0 + n < NN)
            v = *reinterpret_cast<const uint4*>(g_H16 + (size_t)(n0 + n) * 64 + c8 * 8);
        float2 f0 = h2f(v.x), f1 = h2f(v.y), f2 = h2f(v.z), f3 = h2f(v.w);
        int cb = c8 * 8;
        sX[cb + 0][n] = fmaxf(f0.x, 0.f); sX[cb + 1][n] = fmaxf(f0.y, 0.f);
        sX[cb + 2][n] = fmaxf(f1.x, 0.f); sX[cb + 3][n] = fmaxf(f1.y, 0.f);
        sX[cb + 4][n] = fmaxf(f2.x, 0.f); sX[cb + 5][n] = fmaxf(f2.y, 0.f);
        sX[cb + 6][n] = fmaxf(f3.x, 0.f); sX[cb + 7][n] = fmaxf(f3.y, 0.f);
    }

    const int tx = tid & 7;    // 8 col groups x4 = 32 cols
    const int ty = tid >> 3;   // 16 row groups x8 = 128 nodes

    for (int which = 0; which < 3; ++which) {
        __syncthreads();
        for (int i = tid; i < 512; i += 128) {
            int c = i >> 3, o4 = i & 7;
            float4 w = reinterpret_cast<const float4*>(W2 + which * 2048)[c * 8 + o4];
            if (which == 0) {
                float4 w2 = reinterpret_cast<const float4*>(W2 + 2 * 2048)[c * 8 + o4];
                w.x -= w2.x; w.y -= w2.y; w.z -= w2.z; w.w -= w2.w;
            }
            reinterpret_cast<float4*>(&sW[c][0])[o4] = w;
        }
        __syncthreads();

        unsigned long long acc2[4][4];
#pragma unroll
        for (int p = 0; p < 4; p++)
#pragma unroll
            for (int j = 0; j < 4; j++) acc2[p][j] = 0ull;

#pragma unroll 8
        for (int k = 0; k < 64; ++k) {
            const unsigned long long* ap =
                reinterpret_cast<const unsigned long long*>(&sX[k][ty * 8]);
            float4 w = *reinterpret_cast<const float4*>(&sW[k][tx * 4]);
            unsigned long long w2[4] = {pk2(w.x, w.x), pk2(w.y, w.y),
                                        pk2(w.z, w.z), pk2(w.w, w.w)};
#pragma unroll
            for (int p = 0; p < 4; p++) {
                unsigned long long a = ap[p];
#pragma unroll
                for (int j = 0; j < 4; j++) acc2[p][j] = ffma2(a, w2[j], acc2[p][j]);
            }
        }

        float4 bv = make_float4(0.f, 0.f, 0.f, 0.f);
        if (which == 0) bv = reinterpret_cast<const float4*>(b2)[tx];
#pragma unroll
        for (int p = 0; p < 4; p++) {
            float lo[4], hi[4];
#pragma unroll
            for (int j = 0; j < 4; j++) upk2(acc2[p][j], lo[j], hi[j]);
            int n = n0 + ty * 8 + p * 2;
            if (which == 0) {
                if (n < NN)
                    reinterpret_cast<float4*>(out)[(size_t)n * 8 + tx] =
                        make_float4(lo[0] + bv.x, lo[1] + bv.y, lo[2] + bv.z, lo[3] + bv.w);
                if (n + 1 < NN)
                    reinterpret_cast<float4*>(out)[(size_t)(n + 1) * 8 + tx] =
                        make_float4(hi[0] + bv.x, hi[1] + bv.y, hi[2] + bv.z, hi[3] + bv.w);
            } else {
                __half* dst = (which == 1) ? g_B216 : g_C2216;
                if (n < NN)
                    *reinterpret_cast<uint2*>(dst + (size_t)n * 32 + tx * 4) =
                        make_uint2(f2h(lo[0], lo[1]), f2h(lo[2], lo[3]));
                if (n + 1 < NN)
                    *reinterpret_cast<uint2*>(dst + (size_t)(n + 1) * 32 + tx * 4) =
                        make_uint2(f2h(hi[0], hi[1]), f2h(hi[2], hi[3]));
            }
        }
    }
}

// ---------------- fp16 pull propagation --------------------------------------
// G threads per row; each thread owns 8 fp16 channels (one 16B uint4).
// C = G*8 channels. fp32 accumulation; dst is fp16 RMW except MODE 3 (fp32 out).
template <int G, int MODE>
__global__ __launch_bounds__(256) void k_prop16(float* __restrict__ dout, float scale) {
    constexpr int C = G * 8;
    unsigned t = blockIdx.x * 256u + threadIdx.x;
    unsigned r = t / G;
    unsigned g = t & (G - 1);
    if (r >= NN) return;

    const __half* src;
    __half* dsth = nullptr;
    if (MODE == 0)      { src = g_C216;  dsth = g_B16;  }
    else if (MODE == 1) { src = g_B16;   dsth = g_H16;  }
    else if (MODE == 2) { src = g_C2216; dsth = g_B216; }
    else                { src = g_B216; }

    int e  = g_ptr[r];
    int e1 = (r == NN - 1) ? EE : g_ptr[r + 1];

    float a0[8], a1[8];
#pragma unroll
    for (int j = 0; j < 8; j++) { a0[j] = 0.f; a1[j] = 0.f; }

    for (; e + 1 < e1; e += 2) {
        int2 cw0 = __ldg(&g_csr_cw[e]);
        int2 cw1 = __ldg(&g_csr_cw[e + 1]);
        float w0 = __int_as_float(cw0.y);
        float w1 = __int_as_float(cw1.y);
        uint4 v0 = *reinterpret_cast<const uint4*>(src + (size_t)cw0.x * C + g * 8);
        uint4 v1 = *reinterpret_cast<const uint4*>(src + (size_t)cw1.x * C + g * 8);
        float2 f;
        f = h2f(v0.x); a0[0] += w0 * f.x; a0[1] += w0 * f.y;
        f = h2f(v0.y); a0[2] += w0 * f.x; a0[3] += w0 * f.y;
        f = h2f(v0.z); a0[4] += w0 * f.x; a0[5] += w0 * f.y;
        f = h2f(v0.w); a0[6] += w0 * f.x; a0[7] += w0 * f.y;
        f = h2f(v1.x); a1[0] += w1 * f.x; a1[1] += w1 * f.y;
        f = h2f(v1.y); a1[2] += w1 * f.x; a1[3] += w1 * f.y;
        f = h2f(v1.z); a1[4] += w1 * f.x; a1[5] += w1 * f.y;
        f = h2f(v1.w); a1[6] += w1 * f.x; a1[7] += w1 * f.y;
    }
    if (e < e1) {
        int2 cw0 = __ldg(&g_csr_cw[e]);
        float w0 = __int_as_float(cw0.y);
        uint4 v0 = *reinterpret_cast<const uint4*>(src + (size_t)cw0.x * C + g * 8);
        float2 f;
        f = h2f(v0.x); a0[0] += w0 * f.x; a0[1] += w0 * f.y;
        f = h2f(v0.y); a0[2] += w0 * f.x; a0[3] += w0 * f.y;
        f = h2f(v0.z); a0[4] += w0 * f.x; a0[5] += w0 * f.y;
        f = h2f(v0.w); a0[6] += w0 * f.x; a0[7] += w0 * f.y;
    }
#pragma unroll
    for (int j = 0; j < 8; j++) a0[j] = a0[j] + a1[j];

    if (MODE == 3) {
        float* p = dout + (size_t)r * 32 + g * 8;
        float4 d0 = *reinterpret_cast<float4*>(p);
        float4 d1 = *reinterpret_cast<float4*>(p + 4);
        d0.x += scale * a0[0]; d0.y += scale * a0[1];
        d0.z += scale * a0[2]; d0.w += scale * a0[3];
        d1.x += scale * a0[4]; d1.y += scale * a0[5];
        d1.z += scale * a0[6]; d1.w += scale * a0[7];
        *reinterpret_cast<float4*>(p)     = d0;
        *reinterpret_cast<float4*>(p + 4) = d1;
    } else {
        __half* p = dsth + (size_t)r * C + g * 8;
        uint4 dv = *reinterpret_cast<uint4*>(p);
        float2 f0 = h2f(dv.x), f1 = h2f(dv.y), f2 = h2f(dv.z), f3 = h2f(dv.w);
        dv.x = f2h(f0.x + scale * a0[0], f0.y + scale * a0[1]);
        dv.y = f2h(f1.x + scale * a0[2], f1.y + scale * a0[3]);
        dv.z = f2h(f2.x + scale * a0[4], f2.y + scale * a0[5]);
        dv.w = f2h(f3.x + scale * a0[6], f3.y + scale * a0[7]);
        *reinterpret_cast<uint4*>(p) = dv;
    }
}

// ---------------- launch ------------------------------------------------------
extern "C" void kernel_launch(void* const* d_in, const int* in_sizes, int n_in,
                              void* d_out, int out_size) {
    const float* x   = (const float*)d_in[0];
    const int*   ei  = (const int*)d_in[1];     // int32 (JAX x64 disabled)
    const float* W1  = (const float*)d_in[2];
    const float* b1  = (const float*)d_in[3];
    const float* W2  = (const float*)d_in[4];
    const float* b2  = (const float*)d_in[5];
    float*       out = (float*)d_out;

    const int* row = ei;
    const int* col = ei + EE;

    static cudaStream_t s2 = []() {
        cudaStream_t s;
        cudaStreamCreateWithFlags(&s, cudaStreamNonBlocking);
        return s;
    }();
    static cudaEvent_t evFork = []() {
        cudaEvent_t e;
        cudaEventCreateWithFlags(&e, cudaEventDisableTiming);
        return e;
    }();
    static cudaEvent_t evJoin = []() {
        cudaEvent_t e;
        cudaEventCreateWithFlags(&e, cudaEventDisableTiming);
        return e;
    }();

    const int TB = 256;

    // fork: CSR build on s2 (independent of gemm1)
    cudaEventRecord(evFork, 0);
    cudaStreamWaitEvent(s2, evFork, 0);
    k_init <<<(NN + TB - 1) / TB, TB, 0, s2>>>();
    k_deg  <<<(EE + TB - 1) / TB, TB, 0, s2>>>(row);
    k_scan1<<<NB, 1024, 0, s2>>>();
    k_scan3<<<NB, 1024, 0, s2>>>();
    k_fill <<<(EE + TB - 1) / TB, TB, 0, s2>>>(row, col);
    cudaEventRecord(evJoin, s2);

    // concurrent: Layer-1 fused GEMM
    k_gemm1<<<(NN + 63) / 64, 128>>>(x, W1, b1);

    // join: props need CSR + GEMM outputs
    cudaStreamWaitEvent(0, evJoin, 0);

    // B += 2*P(C2)   (P = -A_norm -> scale = -2)
    k_prop16<8, 0><<<((unsigned)NN * 8 + TB - 1) / TB, TB>>>(out, -2.0f);
    // H += P(B)
    k_prop16<8, 1><<<((unsigned)NN * 8 + TB - 1) / TB, TB>>>(out, -1.0f);

    // Layer 2 (relu on load): out = relu(H)@(W0'-W2')+b2, B2, C22
    k_gemm2<<<(NN + 127) / 128, 128>>>(out, W2, b2);
    // B2 += 2*P(C22)
    k_prop16<4, 2><<<((unsigned)NN * 4 + TB - 1) / TB, TB>>>(out, -2.0f);
    // out += P(B2)
    k_prop16<4, 3><<<((unsigned)NN * 4 + TB - 1) / TB, TB>>>(out, -1.0f);
}